// round 13
// baseline (speedup 1.0000x reference)
#include <cuda_runtime.h>
#include <cuda_fp16.h>
#include <cstdint>

#define DI __device__ __forceinline__

// ---------------- persistent prepped weights (mma B-fragment order, 2 ks per uint4) ----------------
__device__ uint4 g_W1q[48 * 8 * 32];
__device__ uint4 g_Wwq[32 * 4 * 32];
__device__ float g_b1[384];
__device__ float g_b2[256];

DI uint32_t packh2(float a, float b) {
    __half2 h = __halves2half2(__float2half_rn(a), __float2half_rn(b));
    return *reinterpret_cast<uint32_t*>(&h);
}

__global__ void prep_kernel(const float* __restrict__ tw, const float* __restrict__ tb,
                            const float* __restrict__ pw, const float* __restrict__ pb,
                            const float* __restrict__ gw, const float* __restrict__ gb,
                            const float* __restrict__ ww, const float* __restrict__ wb,
                            const float* __restrict__ gamma, const float* __restrict__ beta) {
    int idx = blockIdx.x * blockDim.x + threadIdx.x;
    const float inv = rsqrtf(1.0f + 1e-5f);
    if (idx < 48 * 8 * 32) {
        int lane = idx & 31, q = (idx >> 5) & 7, jt = idx >> 8;
        int j = jt * 8 + (lane >> 2);
        int ka = (2 * q) * 16 + (lane & 3) * 2;
        int kb = ka + 16;
        auto W = [&](int jj, int c) -> float {
            return (jj < 128) ? tw[jj * 256 + c]
                 : (jj < 256) ? pw[(jj - 128) * 256 + c]
                              : gw[(jj - 256) * 256 + c];
        };
        uint4 v;
        v.x = packh2(W(j, ka),     W(j, ka + 1));
        v.y = packh2(W(j, ka + 8), W(j, ka + 9));
        v.z = packh2(W(j, kb),     W(j, kb + 1));
        v.w = packh2(W(j, kb + 8), W(j, kb + 9));
        g_W1q[idx] = v;
    }
    if (idx < 32 * 4 * 32) {
        int lane = idx & 31, q = (idx >> 5) & 3, jt = idx >> 7;
        int c = jt * 8 + (lane >> 2);
        int ka = (2 * q) * 16 + (lane & 3) * 2;
        int kb = ka + 16;
        float s = gamma[c] * inv;
        uint4 v;
        v.x = packh2(ww[c * 128 + ka] * s,     ww[c * 128 + ka + 1] * s);
        v.y = packh2(ww[c * 128 + ka + 8] * s, ww[c * 128 + ka + 9] * s);
        v.z = packh2(ww[c * 128 + kb] * s,     ww[c * 128 + kb + 1] * s);
        v.w = packh2(ww[c * 128 + kb + 8] * s, ww[c * 128 + kb + 9] * s);
        g_Wwq[idx] = v;
    }
    if (idx < 384) g_b1[idx] = (idx < 128) ? tb[idx] : ((idx < 256) ? pb[idx - 128] : gb[idx - 256]);
    if (idx < 256) g_b2[idx] = wb[idx] * (gamma[idx] * inv) + beta[idx];
}

// ---------------- helpers ----------------
DI void split2(float a, float b, uint32_t& hi, uint32_t& lo) {
    __half ha = __float2half_rn(a), hb = __float2half_rn(b);
    float la = a - __half2float(ha), lb = b - __half2float(hb);
    __half2 H = __halves2half2(ha, hb);
    hi = *reinterpret_cast<uint32_t*>(&H);
    lo = packh2(la, lb);
}
DI void ldm4(uint32_t* r, uint32_t addr) {
    asm volatile("ldmatrix.sync.aligned.m8n8.x4.shared.b16 {%0,%1,%2,%3}, [%4];\n"
                 : "=r"(r[0]), "=r"(r[1]), "=r"(r[2]), "=r"(r[3]) : "r"(addr));
}
DI void mma16816(float* d, const uint32_t* a, uint32_t b0, uint32_t b1) {
    asm volatile("mma.sync.aligned.m16n8k16.row.col.f32.f16.f16.f32 "
                 "{%0,%1,%2,%3}, {%4,%5,%6,%7}, {%8,%9}, {%0,%1,%2,%3};\n"
                 : "+f"(d[0]), "+f"(d[1]), "+f"(d[2]), "+f"(d[3])
                 : "r"(a[0]), "r"(a[1]), "r"(a[2]), "r"(a[3]), "r"(b0), "r"(b1));
}
DI void mma16816h(uint32_t* d, const uint32_t* a, uint32_t b0, uint32_t b1) {
    asm volatile("mma.sync.aligned.m16n8k16.row.col.f16.f16.f16.f16 "
                 "{%0,%1}, {%2,%3,%4,%5}, {%6,%7}, {%0,%1};\n"
                 : "+r"(d[0]), "+r"(d[1])
                 : "r"(a[0]), "r"(a[1]), "r"(a[2]), "r"(a[3]), "r"(b0), "r"(b1));
}
DI float hmax4(float a, float b, float c, float d) { return fmaxf(fmaxf(a, b), fmaxf(c, d)); }
DI float pool4(float v) {
    v = fmaxf(v, __shfl_xor_sync(0xffffffffu, v, 4));
    v = fmaxf(v, __shfl_xor_sync(0xffffffffu, v, 8));
    return v;
}
DI uint32_t pool4h(uint32_t v) {
    __half2 a = *reinterpret_cast<__half2*>(&v);
    uint32_t u = __shfl_xor_sync(0xffffffffu, v, 4);
    a = __hmax2(a, *reinterpret_cast<__half2*>(&u));
    uint32_t w = *reinterpret_cast<uint32_t*>(&a);
    u = __shfl_xor_sync(0xffffffffu, w, 8);
    a = __hmax2(a, *reinterpret_cast<__half2*>(&u));
    return *reinterpret_cast<uint32_t*>(&a);
}

// ---------------- smem layout (bytes) ----------------
constexpr int OFF_XH = 0;        // half [64][256] swizzled (GEMM1 A, residual hi)  32768 B
constexpr int OFF_XL = 32768;    // half [64][256] swizzled (residual lo)           32768 B
constexpr int OFF_TH = 65536;    // half [64][128] swizzled (theta); WY overlay     16384 B
constexpr int OFF_YB = 81920;    // half [64][128] swizzled (y); WY overlay         16384 B
constexpr int OFF_PH = 98304;    // half [16][136] phi pooled                        4352 B
constexpr int OFF_GX = 102656;   // half [128][16] gx pooled (i-major)               4096 B
constexpr int OFF_B1 = 106752;   // float[384]
constexpr int OFF_B2 = 108288;   // float[256]
constexpr int OFF_GO = 109312;   // int[64]
constexpr int OFF_ATT = 109568;  // uint32[64][9] attention fragments               2304 B
constexpr int SMEM_BYTES = 111872;
// WY: uint32[64][132] at OFF_TH (33792 B, spans TH+YB, both dead in phase-4 tail)

__global__ void __launch_bounds__(256, 2)
nl_kernel(const float* __restrict__ x, const int* __restrict__ grouped,
          float* __restrict__ out) {
    extern __shared__ char smem[];
    const uint32_t sbase = (uint32_t)__cvta_generic_to_shared(smem);
    float* b1s = (float*)(smem + OFF_B1);
    float* b2s = (float*)(smem + OFF_B2);
    int*   gos = (int*)(smem + OFF_GO);

    const int tid = threadIdx.x, warp = tid >> 5, lane = tid & 31;
    const int g = lane >> 2, t = lane & 3;
    const int blk = blockIdx.x;

    // ---- phase 0: tables ----
    if (tid < 64) gos[tid] = grouped[tid];
    b2s[tid] = g_b2[tid];
    b1s[tid] = g_b1[tid];
    if (tid < 128) b1s[256 + tid] = g_b1[256 + tid];
    __syncthreads();

    // ---- phase 1: gather rows by grouped order; hi/lo fp16 split, both swizzled ----
    {
        const float4* x4 = (const float4*)x;
        uint4* XH4 = (uint4*)(smem + OFF_XH);
        uint4* XL4 = (uint4*)(smem + OFF_XL);
#pragma unroll
        for (int it = 0; it < 8; it++) {
            int ci = tid + it * 256;
            int r = ci >> 5, ch = ci & 31;
            size_t rb = ((size_t)blk * 64 + gos[r]) * 64;
            float4 va = x4[rb + ch * 2];
            float4 vb = x4[rb + ch * 2 + 1];
            float f[8] = {va.x, va.y, va.z, va.w, vb.x, vb.y, vb.z, vb.w};
            uint32_t hw[4], lw[4];
#pragma unroll
            for (int q = 0; q < 4; q++) split2(f[2 * q], f[2 * q + 1], hw[q], lw[q]);
            int pos = r * 32 + (ch ^ (r & 7));
            XH4[pos] = make_uint4(hw[0], hw[1], hw[2], hw[3]);
            XL4[pos] = make_uint4(lw[0], lw[1], lw[2], lw[3]);
        }
    }
    __syncthreads();

    // ---- phase 2: GEMM1  Out1[64][384] = Xg @ W1^T, single pass ----
    const int colA = warp * 32;
    const int colG = 256 + warp * 16;
    {
        float    accA[4][4][4];
        uint32_t accG[4][2][2];
#pragma unroll
        for (int a_ = 0; a_ < 4; a_++)
#pragma unroll
            for (int b_ = 0; b_ < 4; b_++) {
#pragma unroll
                for (int c_ = 0; c_ < 4; c_++) accA[a_][b_][c_] = 0.f;
                if (b_ < 2) { accG[a_][b_][0] = 0u; accG[a_][b_][1] = 0u; }
            }

        for (int q = 0; q < 8; q++) {
            uint4 wq[4], wg[2];
#pragma unroll
            for (int b_ = 0; b_ < 4; b_++) wq[b_] = g_W1q[((warp * 4 + b_) * 8 + q) * 32 + lane];
#pragma unroll
            for (int b_ = 0; b_ < 2; b_++) wg[b_] = g_W1q[((32 + warp * 2 + b_) * 8 + q) * 32 + lane];
#pragma unroll
            for (int hf = 0; hf < 2; hf++) {
                int ks = q * 2 + hf;
                uint32_t ah[4][4];
                int rr = lane & 15, hk = lane >> 4;
#pragma unroll
                for (int mt = 0; mt < 4; mt++) {
                    int r = mt * 16 + rr, ch = ks * 2 + hk;
                    ldm4(ah[mt], sbase + OFF_XH + r * 512 + ((ch ^ (r & 7)) << 4));
                }
#pragma unroll
                for (int b_ = 0; b_ < 4; b_++) {
                    uint32_t b0 = hf ? wq[b_].z : wq[b_].x;
                    uint32_t b1 = hf ? wq[b_].w : wq[b_].y;
#pragma unroll
                    for (int mt = 0; mt < 4; mt++) mma16816(accA[mt][b_], ah[mt], b0, b1);
                }
#pragma unroll
                for (int b_ = 0; b_ < 2; b_++) {
                    uint32_t b0 = hf ? wg[b_].z : wg[b_].x;
                    uint32_t b1 = hf ? wg[b_].w : wg[b_].y;
#pragma unroll
                    for (int mt = 0; mt < 4; mt++) mma16816h(accG[mt][b_], ah[mt], b0, b1);
                }
            }
        }

        // ---- epilogue: theta store (warps 0-3), phi pool+store (warps 4-7), g pool (all) ----
        uint32_t* TH = (uint32_t*)(smem + OFF_TH);
        uint32_t* PH = (uint32_t*)(smem + OFF_PH);
        __half*   GX = (__half*)(smem + OFF_GX);
#pragma unroll
        for (int b_ = 0; b_ < 4; b_++) {
            int c = colA + b_ * 8 + t * 2;
            float bi0 = b1s[c], bi1 = b1s[c + 1];
#pragma unroll
            for (int mt = 0; mt < 4; mt++) {
                float v00 = accA[mt][b_][0] + bi0, v01 = accA[mt][b_][1] + bi1;
                float v10 = accA[mt][b_][2] + bi0, v11 = accA[mt][b_][3] + bi1;
                if (warp < 4) {
                    int r0 = mt * 16 + g, r1 = r0 + 8;
                    int wd = c >> 1, chn = c >> 3;
                    TH[r0 * 64 + (((chn ^ (r0 & 7)) << 2) | (wd & 3))] = packh2(v00, v01);
                    TH[r1 * 64 + (((chn ^ (r1 & 7)) << 2) | (wd & 3))] = packh2(v10, v11);
                } else {
                    v00 = pool4(v00); v01 = pool4(v01);
                    v10 = pool4(v10); v11 = pool4(v11);
                    if ((g & 3) == 0) {
                        int i = c - 128;
                        int p01 = mt * 4 + (g >> 2), p23 = p01 + 2;
                        PH[p01 * 68 + (i >> 1)] = packh2(v00, v01);
                        PH[p23 * 68 + (i >> 1)] = packh2(v10, v11);
                    }
                }
            }
        }
        // g pooled (f16 accums) -> GX[i][p]
#pragma unroll
        for (int b_ = 0; b_ < 2; b_++) {
            int c = colG + b_ * 8 + t * 2;
            int i = c - 256;
            float bi0 = b1s[c], bi1 = b1s[c + 1];
#pragma unroll
            for (int mt = 0; mt < 4; mt++) {
                uint32_t u0 = pool4h(accG[mt][b_][0]);
                uint32_t u1 = pool4h(accG[mt][b_][1]);
                if ((g & 3) == 0) {
                    __half2 h0 = *reinterpret_cast<__half2*>(&u0);
                    __half2 h1 = *reinterpret_cast<__half2*>(&u1);
                    float v00 = __low2float(h0) + bi0, v01 = __high2float(h0) + bi1;
                    float v10 = __low2float(h1) + bi0, v11 = __high2float(h1) + bi1;
                    int p01 = mt * 4 + (g >> 2), p23 = p01 + 2;
                    GX[i * 16 + p01]       = __float2half_rn(v00);
                    GX[(i + 1) * 16 + p01] = __float2half_rn(v01);
                    GX[i * 16 + p23]       = __float2half_rn(v10);
                    GX[(i + 1) * 16 + p23] = __float2half_rn(v11);
                }
            }
        }
    }

    // prefetch first phase-4 weight pair (hides L2 latency behind phase 3)
    uint4 wpre0 = g_Wwq[((warp * 4 + 0) * 4 + 0) * 32 + lane];
    uint4 wpre1 = g_Wwq[((warp * 4 + 1) * 4 + 0) * 32 + lane];
    __syncthreads();

    // ---- phase 3a (warps 0-3): f = theta @ phiP^T, softmax, stage attention ----
    uint32_t* ATT = (uint32_t*)(smem + OFF_ATT);
    if (warp < 4) {
        float accF[2][4];
#pragma unroll
        for (int n_ = 0; n_ < 2; n_++)
#pragma unroll
            for (int c_ = 0; c_ < 4; c_++) accF[n_][c_] = 0.f;

        const __half* PHh = (const __half*)(smem + OFF_PH);
        for (int ks = 0; ks < 8; ks++) {
            uint32_t th[4];
            int r = warp * 16 + (lane & 15), ch = ks * 2 + (lane >> 4);
            ldm4(th, sbase + OFF_TH + r * 256 + ((ch ^ (r & 7)) << 4));
#pragma unroll
            for (int n_ = 0; n_ < 2; n_++) {
                int m = n_ * 8 + g;
                const uint32_t* bh = (const uint32_t*)(PHh + m * 136 + ks * 16 + t * 2);
                mma16816(accF[n_], th, bh[0], bh[4]);
            }
        }
        float a0 = accF[0][0], a1 = accF[0][1], a2 = accF[1][0], a3 = accF[1][1];
        float c0 = accF[0][2], c1 = accF[0][3], c2 = accF[1][2], c3 = accF[1][3];
        float mA = hmax4(a0, a1, a2, a3), mB = hmax4(c0, c1, c2, c3);
        mA = fmaxf(mA, __shfl_xor_sync(0xffffffffu, mA, 1));
        mA = fmaxf(mA, __shfl_xor_sync(0xffffffffu, mA, 2));
        mB = fmaxf(mB, __shfl_xor_sync(0xffffffffu, mB, 1));
        mB = fmaxf(mB, __shfl_xor_sync(0xffffffffu, mB, 2));
        a0 = __expf(a0 - mA); a1 = __expf(a1 - mA); a2 = __expf(a2 - mA); a3 = __expf(a3 - mA);
        c0 = __expf(c0 - mB); c1 = __expf(c1 - mB); c2 = __expf(c2 - mB); c3 = __expf(c3 - mB);
        float sA = a0 + a1 + a2 + a3, sB = c0 + c1 + c2 + c3;
        sA += __shfl_xor_sync(0xffffffffu, sA, 1);
        sA += __shfl_xor_sync(0xffffffffu, sA, 2);
        sB += __shfl_xor_sync(0xffffffffu, sB, 1);
        sB += __shfl_xor_sync(0xffffffffu, sB, 2);
        float iA = 1.0f / sA, iB = 1.0f / sB;
        a0 *= iA; a1 *= iA; a2 *= iA; a3 *= iA;
        c0 *= iB; c1 *= iB; c2 *= iB; c3 *= iB;
        int rA = warp * 16 + g;
        ATT[rA * 9 + t]           = packh2(a0, a1);
        ATT[(rA + 8) * 9 + t]     = packh2(c0, c1);
        ATT[rA * 9 + t + 4]       = packh2(a2, a3);
        ATT[(rA + 8) * 9 + t + 4] = packh2(c2, c3);
    }
    __syncthreads();

    // ---- phase 3b (all 8 warps): y = a @ gx, each warp does 8 n-tiles ----
    {
        int rowBase = (warp & 3) * 16;
        int ntBase = (warp >> 2) * 8;
        uint32_t fa2[4];
        fa2[0] = ATT[(rowBase + g) * 9 + t];
        fa2[1] = ATT[(rowBase + g + 8) * 9 + t];
        fa2[2] = ATT[(rowBase + g) * 9 + t + 4];
        fa2[3] = ATT[(rowBase + g + 8) * 9 + t + 4];

        float accY[8][4];
#pragma unroll
        for (int nt = 0; nt < 8; nt++)
#pragma unroll
            for (int c_ = 0; c_ < 4; c_++) accY[nt][c_] = 0.f;
        const __half* GX = (const __half*)(smem + OFF_GX);
#pragma unroll
        for (int nt = 0; nt < 8; nt++) {
            int irow = (ntBase + nt) * 8 + g;
            const uint32_t* bp = (const uint32_t*)(GX + irow * 16 + t * 2);
            mma16816(accY[nt], fa2, bp[0], bp[4]);
        }
        uint32_t* YB = (uint32_t*)(smem + OFF_YB);
        int r0 = rowBase + g, r1 = r0 + 8;
#pragma unroll
        for (int nt = 0; nt < 8; nt++) {
            int rn = ntBase + nt;
            YB[r0 * 64 + (((rn ^ (r0 & 7)) << 2) | t)] = packh2(accY[nt][0], accY[nt][1]);
            YB[r1 * 64 + (((rn ^ (r1 & 7)) << 2) | t)] = packh2(accY[nt][2], accY[nt][3]);
        }
    }
    __syncthreads();

    // ---- phase 4: wy[64][256] = y @ Ww^T (f16 acc) ----
    uint32_t accW[4][4][2];
#pragma unroll
    for (int a_ = 0; a_ < 4; a_++)
#pragma unroll
        for (int b_ = 0; b_ < 4; b_++) { accW[a_][b_][0] = 0u; accW[a_][b_][1] = 0u; }

#pragma unroll
    for (int q = 0; q < 4; q++) {
        uint4 wq[4];
#pragma unroll
        for (int b_ = 0; b_ < 4; b_++) {
            if (q == 0 && b_ == 0) wq[b_] = wpre0;
            else if (q == 0 && b_ == 1) wq[b_] = wpre1;
            else wq[b_] = g_Wwq[((warp * 4 + b_) * 4 + q) * 32 + lane];
        }
#pragma unroll
        for (int hf = 0; hf < 2; hf++) {
            int ks = q * 2 + hf;
            uint32_t ya[4][4];
            int rr = lane & 15, hk = lane >> 4;
#pragma unroll
            for (int mt = 0; mt < 4; mt++) {
                int r = mt * 16 + rr, ch = ks * 2 + hk;
                ldm4(ya[mt], sbase + OFF_YB + r * 256 + ((ch ^ (r & 7)) << 4));
            }
#pragma unroll
            for (int b_ = 0; b_ < 4; b_++) {
                uint32_t b0 = hf ? wq[b_].z : wq[b_].x;
                uint32_t b1 = hf ? wq[b_].w : wq[b_].y;
#pragma unroll
                for (int mt = 0; mt < 4; mt++) mma16816h(accW[mt][b_], ya[mt], b0, b1);
            }
        }
    }

    // ---- phase 4b: stage wy pairs in smem (bank-conflict-free), then coalesced epilogue ----
    __syncthreads();   // all YB reads complete; TH/YB reusable as WY
    {
        uint32_t* WY = (uint32_t*)(smem + OFF_TH);   // [64 rows][132 words]
#pragma unroll
        for (int b_ = 0; b_ < 4; b_++) {
            int p = warp * 16 + b_ * 4 + t;
#pragma unroll
            for (int mt = 0; mt < 4; mt++) {
#pragma unroll
                for (int h_ = 0; h_ < 2; h_++) {
                    int r = mt * 16 + g + h_ * 8;
                    WY[r * 132 + p] = accW[mt][b_][h_];
                }
            }
        }
    }
    __syncthreads();
    {
        const uint32_t* WY = (const uint32_t*)(smem + OFF_TH);
        float4* out4 = (float4*)out;
#pragma unroll
        for (int it = 0; it < 16; it++) {
            int id = tid + it * 256;
            int row = id >> 6, c4 = id & 63;
            uint32_t chn = (uint32_t)((c4 >> 1) ^ (row & 7));
            const char* xb = smem + OFF_XH + row * 512 + chn * 16 + (c4 & 1) * 8;
            uint2 xh2 = *(const uint2*)xb;
            uint2 xl2 = *(const uint2*)(xb + 32768);
            uint2 wy2 = *(const uint2*)(WY + row * 132 + c4 * 2);
            float4 bb = *(const float4*)(b2s + c4 * 4);
            __half2 H0 = *reinterpret_cast<__half2*>(&xh2.x);
            __half2 H1 = *reinterpret_cast<__half2*>(&xh2.y);
            __half2 L0 = *reinterpret_cast<__half2*>(&xl2.x);
            __half2 L1 = *reinterpret_cast<__half2*>(&xl2.y);
            __half2 W0 = *reinterpret_cast<__half2*>(&wy2.x);
            __half2 W1 = *reinterpret_cast<__half2*>(&wy2.y);
            __half2 WL0 = __hadd2(W0, L0);
            __half2 WL1 = __hadd2(W1, L1);
            float4 o;
            o.x = __low2float(WL0)  + bb.x + __low2float(H0);
            o.y = __high2float(WL0) + bb.y + __high2float(H0);
            o.z = __low2float(WL1)  + bb.z + __low2float(H1);
            o.w = __high2float(WL1) + bb.w + __high2float(H1);
            out4[((size_t)blk * 64 + gos[row]) * 64 + c4] = o;
        }
    }
}

extern "C" void kernel_launch(void* const* d_in, const int* in_sizes, int n_in,
                              void* d_out, int out_size) {
    const float* x       = (const float*)d_in[0];
    const int*   grouped = (const int*)d_in[1];
    const float* tw  = (const float*)d_in[3];
    const float* tb  = (const float*)d_in[4];
    const float* pw  = (const float*)d_in[5];
    const float* pb  = (const float*)d_in[6];
    const float* gw  = (const float*)d_in[7];
    const float* gb  = (const float*)d_in[8];
    const float* ww  = (const float*)d_in[9];
    const float* wb  = (const float*)d_in[10];
    const float* gam = (const float*)d_in[11];
    const float* bet = (const float*)d_in[12];
    float* out = (float*)d_out;

    prep_kernel<<<48, 256>>>(tw, tb, pw, pb, gw, gb, ww, wb, gam, bet);
    cudaFuncSetAttribute(nl_kernel, cudaFuncAttributeMaxDynamicSharedMemorySize, SMEM_BYTES);
    nl_kernel<<<4096, 256, SMEM_BYTES>>>(x, grouped, out);
}

// round 14
// speedup vs baseline: 1.4340x; 1.4340x over previous
#include <cuda_runtime.h>
#include <cuda_fp16.h>
#include <cstdint>

#define DI __device__ __forceinline__

// ---------------- persistent prepped weights (mma B-fragment order, 2 ks per uint4) ----------------
__device__ uint4 g_W1q[48 * 8 * 32];
__device__ uint4 g_Wwq[32 * 4 * 32];
__device__ float g_b1[384];
__device__ float g_b2[256];

DI uint32_t packh2(float a, float b) {
    __half2 h = __halves2half2(__float2half_rn(a), __float2half_rn(b));
    return *reinterpret_cast<uint32_t*>(&h);
}

__global__ void prep_kernel(const float* __restrict__ tw, const float* __restrict__ tb,
                            const float* __restrict__ pw, const float* __restrict__ pb,
                            const float* __restrict__ gw, const float* __restrict__ gb,
                            const float* __restrict__ ww, const float* __restrict__ wb,
                            const float* __restrict__ gamma, const float* __restrict__ beta) {
    int idx = blockIdx.x * blockDim.x + threadIdx.x;
    const float inv = rsqrtf(1.0f + 1e-5f);
    if (idx < 48 * 8 * 32) {
        int lane = idx & 31, q = (idx >> 5) & 7, jt = idx >> 8;
        int j = jt * 8 + (lane >> 2);
        int ka = (2 * q) * 16 + (lane & 3) * 2;
        int kb = ka + 16;
        auto W = [&](int jj, int c) -> float {
            return (jj < 128) ? tw[jj * 256 + c]
                 : (jj < 256) ? pw[(jj - 128) * 256 + c]
                              : gw[(jj - 256) * 256 + c];
        };
        uint4 v;
        v.x = packh2(W(j, ka),     W(j, ka + 1));
        v.y = packh2(W(j, ka + 8), W(j, ka + 9));
        v.z = packh2(W(j, kb),     W(j, kb + 1));
        v.w = packh2(W(j, kb + 8), W(j, kb + 9));
        g_W1q[idx] = v;
    }
    if (idx < 32 * 4 * 32) {
        int lane = idx & 31, q = (idx >> 5) & 3, jt = idx >> 7;
        int c = jt * 8 + (lane >> 2);
        int ka = (2 * q) * 16 + (lane & 3) * 2;
        int kb = ka + 16;
        float s = gamma[c] * inv;
        uint4 v;
        v.x = packh2(ww[c * 128 + ka] * s,     ww[c * 128 + ka + 1] * s);
        v.y = packh2(ww[c * 128 + ka + 8] * s, ww[c * 128 + ka + 9] * s);
        v.z = packh2(ww[c * 128 + kb] * s,     ww[c * 128 + kb + 1] * s);
        v.w = packh2(ww[c * 128 + kb + 8] * s, ww[c * 128 + kb + 9] * s);
        g_Wwq[idx] = v;
    }
    if (idx < 384) g_b1[idx] = (idx < 128) ? tb[idx] : ((idx < 256) ? pb[idx - 128] : gb[idx - 256]);
    if (idx < 256) g_b2[idx] = wb[idx] * (gamma[idx] * inv) + beta[idx];
}

// ---------------- helpers ----------------
DI void split2(float a, float b, uint32_t& hi, uint32_t& lo) {
    __half ha = __float2half_rn(a), hb = __float2half_rn(b);
    float la = a - __half2float(ha), lb = b - __half2float(hb);
    __half2 H = __halves2half2(ha, hb);
    hi = *reinterpret_cast<uint32_t*>(&H);
    lo = packh2(la, lb);
}
DI void ldm4(uint32_t* r, uint32_t addr) {
    asm volatile("ldmatrix.sync.aligned.m8n8.x4.shared.b16 {%0,%1,%2,%3}, [%4];\n"
                 : "=r"(r[0]), "=r"(r[1]), "=r"(r[2]), "=r"(r[3]) : "r"(addr));
}
DI void mma16816(float* d, const uint32_t* a, uint32_t b0, uint32_t b1) {
    asm volatile("mma.sync.aligned.m16n8k16.row.col.f32.f16.f16.f32 "
                 "{%0,%1,%2,%3}, {%4,%5,%6,%7}, {%8,%9}, {%0,%1,%2,%3};\n"
                 : "+f"(d[0]), "+f"(d[1]), "+f"(d[2]), "+f"(d[3])
                 : "r"(a[0]), "r"(a[1]), "r"(a[2]), "r"(a[3]), "r"(b0), "r"(b1));
}
DI void mma16816h(uint32_t* d, const uint32_t* a, uint32_t b0, uint32_t b1) {
    asm volatile("mma.sync.aligned.m16n8k16.row.col.f16.f16.f16.f16 "
                 "{%0,%1}, {%2,%3,%4,%5}, {%6,%7}, {%0,%1};\n"
                 : "+r"(d[0]), "+r"(d[1])
                 : "r"(a[0]), "r"(a[1]), "r"(a[2]), "r"(a[3]), "r"(b0), "r"(b1));
}
DI float hmax4(float a, float b, float c, float d) { return fmaxf(fmaxf(a, b), fmaxf(c, d)); }
DI float pool4(float v) {
    v = fmaxf(v, __shfl_xor_sync(0xffffffffu, v, 4));
    v = fmaxf(v, __shfl_xor_sync(0xffffffffu, v, 8));
    return v;
}
DI uint32_t pool4h(uint32_t v) {
    __half2 a = *reinterpret_cast<__half2*>(&v);
    uint32_t u = __shfl_xor_sync(0xffffffffu, v, 4);
    a = __hmax2(a, *reinterpret_cast<__half2*>(&u));
    uint32_t w = *reinterpret_cast<uint32_t*>(&a);
    u = __shfl_xor_sync(0xffffffffu, w, 8);
    a = __hmax2(a, *reinterpret_cast<__half2*>(&u));
    return *reinterpret_cast<uint32_t*>(&a);
}

// ---------------- smem layout (bytes) ----------------
constexpr int OFF_XH = 0;        // half [64][256] swizzled (GEMM1 A, residual hi)  32768 B
constexpr int OFF_XL = 32768;    // half [64][256] swizzled (residual lo)           32768 B
constexpr int OFF_TH = 65536;    // half [64][128] swizzled (theta); WY overlay     16384 B
constexpr int OFF_YB = 81920;    // half [64][128] swizzled (y); WY overlay         16384 B
constexpr int OFF_PH = 98304;    // half [16][136] phi pooled                        4352 B
constexpr int OFF_GX = 102656;   // half [128][16] gx pooled (i-major)               4096 B
constexpr int OFF_B1 = 106752;   // float[384]
constexpr int OFF_B2 = 108288;   // float[256]
constexpr int OFF_GO = 109312;   // int[64]
constexpr int SMEM_BYTES = 109568;
// WY: uint32[64][132] at OFF_TH (33792 B, spans TH+YB, both dead in phase-4 tail)

__global__ void __launch_bounds__(256, 2)
nl_kernel(const float* __restrict__ x, const int* __restrict__ grouped,
          float* __restrict__ out) {
    extern __shared__ char smem[];
    const uint32_t sbase = (uint32_t)__cvta_generic_to_shared(smem);
    float* b1s = (float*)(smem + OFF_B1);
    float* b2s = (float*)(smem + OFF_B2);
    int*   gos = (int*)(smem + OFF_GO);

    const int tid = threadIdx.x, warp = tid >> 5, lane = tid & 31;
    const int g = lane >> 2, t = lane & 3;
    const int blk = blockIdx.x;

    // ---- phase 0: tables ----
    if (tid < 64) gos[tid] = grouped[tid];
    b2s[tid] = g_b2[tid];
    b1s[tid] = g_b1[tid];
    if (tid < 128) b1s[256 + tid] = g_b1[256 + tid];
    __syncthreads();

    // ---- phase 1: gather rows by grouped order; hi/lo fp16 split, both swizzled ----
    {
        const float4* x4 = (const float4*)x;
        uint4* XH4 = (uint4*)(smem + OFF_XH);
        uint4* XL4 = (uint4*)(smem + OFF_XL);
#pragma unroll
        for (int it = 0; it < 8; it++) {
            int ci = tid + it * 256;            // 0..2047 : 64 rows x 32 chunks of 8 floats
            int r = ci >> 5, ch = ci & 31;
            size_t rb = ((size_t)blk * 64 + gos[r]) * 64;
            float4 va = x4[rb + ch * 2];
            float4 vb = x4[rb + ch * 2 + 1];
            float f[8] = {va.x, va.y, va.z, va.w, vb.x, vb.y, vb.z, vb.w};
            uint32_t hw[4], lw[4];
#pragma unroll
            for (int q = 0; q < 4; q++) split2(f[2 * q], f[2 * q + 1], hw[q], lw[q]);
            int pos = r * 32 + (ch ^ (r & 7));
            XH4[pos] = make_uint4(hw[0], hw[1], hw[2], hw[3]);
            XL4[pos] = make_uint4(lw[0], lw[1], lw[2], lw[3]);
        }
    }
    __syncthreads();

    // ---- phase 2: GEMM1  Out1[64][384] = Xg @ W1^T, single pass ----
    const int colA = warp * 32;
    const int colG = 256 + warp * 16;
    {
        float    accA[4][4][4];
        uint32_t accG[4][2][2];
#pragma unroll
        for (int a_ = 0; a_ < 4; a_++)
#pragma unroll
            for (int b_ = 0; b_ < 4; b_++) {
#pragma unroll
                for (int c_ = 0; c_ < 4; c_++) accA[a_][b_][c_] = 0.f;
                if (b_ < 2) { accG[a_][b_][0] = 0u; accG[a_][b_][1] = 0u; }
            }

        for (int q = 0; q < 8; q++) {
            uint4 wq[4], wg[2];
#pragma unroll
            for (int b_ = 0; b_ < 4; b_++) wq[b_] = g_W1q[((warp * 4 + b_) * 8 + q) * 32 + lane];
#pragma unroll
            for (int b_ = 0; b_ < 2; b_++) wg[b_] = g_W1q[((32 + warp * 2 + b_) * 8 + q) * 32 + lane];
#pragma unroll
            for (int hf = 0; hf < 2; hf++) {
                int ks = q * 2 + hf;
                uint32_t ah[4][4];
                int rr = lane & 15, hk = lane >> 4;
#pragma unroll
                for (int mt = 0; mt < 4; mt++) {
                    int r = mt * 16 + rr, ch = ks * 2 + hk;
                    ldm4(ah[mt], sbase + OFF_XH + r * 512 + ((ch ^ (r & 7)) << 4));
                }
#pragma unroll
                for (int b_ = 0; b_ < 4; b_++) {
                    uint32_t b0 = hf ? wq[b_].z : wq[b_].x;
                    uint32_t b1 = hf ? wq[b_].w : wq[b_].y;
#pragma unroll
                    for (int mt = 0; mt < 4; mt++) mma16816(accA[mt][b_], ah[mt], b0, b1);
                }
#pragma unroll
                for (int b_ = 0; b_ < 2; b_++) {
                    uint32_t b0 = hf ? wg[b_].z : wg[b_].x;
                    uint32_t b1 = hf ? wg[b_].w : wg[b_].y;
#pragma unroll
                    for (int mt = 0; mt < 4; mt++) mma16816h(accG[mt][b_], ah[mt], b0, b1);
                }
            }
        }

        // ---- epilogue: theta store (warps 0-3), phi pool+store (warps 4-7), g pool (all) ----
        uint32_t* TH = (uint32_t*)(smem + OFF_TH);
        uint32_t* PH = (uint32_t*)(smem + OFF_PH);
        __half*   GX = (__half*)(smem + OFF_GX);
#pragma unroll
        for (int b_ = 0; b_ < 4; b_++) {
            int c = colA + b_ * 8 + t * 2;
            float bi0 = b1s[c], bi1 = b1s[c + 1];
#pragma unroll
            for (int mt = 0; mt < 4; mt++) {
                float v00 = accA[mt][b_][0] + bi0, v01 = accA[mt][b_][1] + bi1;
                float v10 = accA[mt][b_][2] + bi0, v11 = accA[mt][b_][3] + bi1;
                if (warp < 4) {
                    int r0 = mt * 16 + g, r1 = r0 + 8;
                    int wd = c >> 1, chn = c >> 3;
                    TH[r0 * 64 + (((chn ^ (r0 & 7)) << 2) | (wd & 3))] = packh2(v00, v01);
                    TH[r1 * 64 + (((chn ^ (r1 & 7)) << 2) | (wd & 3))] = packh2(v10, v11);
                } else {
                    v00 = pool4(v00); v01 = pool4(v01);
                    v10 = pool4(v10); v11 = pool4(v11);
                    if ((g & 3) == 0) {
                        int i = c - 128;
                        int p01 = mt * 4 + (g >> 2), p23 = p01 + 2;
                        PH[p01 * 68 + (i >> 1)] = packh2(v00, v01);
                        PH[p23 * 68 + (i >> 1)] = packh2(v10, v11);
                    }
                }
            }
        }
        // g pooled (f16 accums) -> GX[i][p]
#pragma unroll
        for (int b_ = 0; b_ < 2; b_++) {
            int c = colG + b_ * 8 + t * 2;
            int i = c - 256;
            float bi0 = b1s[c], bi1 = b1s[c + 1];
#pragma unroll
            for (int mt = 0; mt < 4; mt++) {
                uint32_t u0 = pool4h(accG[mt][b_][0]);
                uint32_t u1 = pool4h(accG[mt][b_][1]);
                if ((g & 3) == 0) {
                    __half2 h0 = *reinterpret_cast<__half2*>(&u0);
                    __half2 h1 = *reinterpret_cast<__half2*>(&u1);
                    float v00 = __low2float(h0) + bi0, v01 = __high2float(h0) + bi1;
                    float v10 = __low2float(h1) + bi0, v11 = __high2float(h1) + bi1;
                    int p01 = mt * 4 + (g >> 2), p23 = p01 + 2;
                    GX[i * 16 + p01]       = __float2half_rn(v00);
                    GX[(i + 1) * 16 + p01] = __float2half_rn(v01);
                    GX[i * 16 + p23]       = __float2half_rn(v10);
                    GX[(i + 1) * 16 + p23] = __float2half_rn(v11);
                }
            }
        }
    }
    __syncthreads();

    // ---- phase 3 (warps 0-3): f = theta @ phiP^T, softmax, y = a @ gx ----
    if (warp < 4) {
        float accF[2][4];
#pragma unroll
        for (int n_ = 0; n_ < 2; n_++)
#pragma unroll
            for (int c_ = 0; c_ < 4; c_++) accF[n_][c_] = 0.f;

        const __half* PHh = (const __half*)(smem + OFF_PH);
        for (int ks = 0; ks < 8; ks++) {
            uint32_t th[4];
            int r = warp * 16 + (lane & 15), ch = ks * 2 + (lane >> 4);
            ldm4(th, sbase + OFF_TH + r * 256 + ((ch ^ (r & 7)) << 4));
#pragma unroll
            for (int n_ = 0; n_ < 2; n_++) {
                int m = n_ * 8 + g;
                const uint32_t* bh = (const uint32_t*)(PHh + m * 136 + ks * 16 + t * 2);
                mma16816(accF[n_], th, bh[0], bh[4]);
            }
        }
        float a0 = accF[0][0], a1 = accF[0][1], a2 = accF[1][0], a3 = accF[1][1];
        float c0 = accF[0][2], c1 = accF[0][3], c2 = accF[1][2], c3 = accF[1][3];
        float mA = hmax4(a0, a1, a2, a3), mB = hmax4(c0, c1, c2, c3);
        mA = fmaxf(mA, __shfl_xor_sync(0xffffffffu, mA, 1));
        mA = fmaxf(mA, __shfl_xor_sync(0xffffffffu, mA, 2));
        mB = fmaxf(mB, __shfl_xor_sync(0xffffffffu, mB, 1));
        mB = fmaxf(mB, __shfl_xor_sync(0xffffffffu, mB, 2));
        a0 = __expf(a0 - mA); a1 = __expf(a1 - mA); a2 = __expf(a2 - mA); a3 = __expf(a3 - mA);
        c0 = __expf(c0 - mB); c1 = __expf(c1 - mB); c2 = __expf(c2 - mB); c3 = __expf(c3 - mB);
        float sA = a0 + a1 + a2 + a3, sB = c0 + c1 + c2 + c3;
        sA += __shfl_xor_sync(0xffffffffu, sA, 1);
        sA += __shfl_xor_sync(0xffffffffu, sA, 2);
        sB += __shfl_xor_sync(0xffffffffu, sB, 1);
        sB += __shfl_xor_sync(0xffffffffu, sB, 2);
        float iA = 1.0f / sA, iB = 1.0f / sB;
        a0 *= iA; a1 *= iA; a2 *= iA; a3 *= iA;
        c0 *= iB; c1 *= iB; c2 *= iB; c3 *= iB;
        uint32_t fa[4];
        fa[0] = packh2(a0, a1); fa[1] = packh2(c0, c1);
        fa[2] = packh2(a2, a3); fa[3] = packh2(c2, c3);

        float accY[16][4];
#pragma unroll
        for (int nt = 0; nt < 16; nt++)
#pragma unroll
            for (int c_ = 0; c_ < 4; c_++) accY[nt][c_] = 0.f;
        const __half* GX = (const __half*)(smem + OFF_GX);
#pragma unroll
        for (int nt = 0; nt < 16; nt++) {
            int irow = nt * 8 + g;
            const uint32_t* bp = (const uint32_t*)(GX + irow * 16 + t * 2);
            mma16816(accY[nt], fa, bp[0], bp[4]);
        }
        uint32_t* YB = (uint32_t*)(smem + OFF_YB);
        int r0 = warp * 16 + g, r1 = r0 + 8;
#pragma unroll
        for (int nt = 0; nt < 16; nt++) {
            YB[r0 * 64 + (((nt ^ (r0 & 7)) << 2) | t)] = packh2(accY[nt][0], accY[nt][1]);
            YB[r1 * 64 + (((nt ^ (r1 & 7)) << 2) | t)] = packh2(accY[nt][2], accY[nt][3]);
        }
    }
    __syncthreads();

    // ---- phase 4: wy[64][256] = y @ Ww^T (f16 acc) ----
    uint32_t accW[4][4][2];
#pragma unroll
    for (int a_ = 0; a_ < 4; a_++)
#pragma unroll
        for (int b_ = 0; b_ < 4; b_++) { accW[a_][b_][0] = 0u; accW[a_][b_][1] = 0u; }

    for (int q = 0; q < 4; q++) {
        uint4 wq[4];
#pragma unroll
        for (int b_ = 0; b_ < 4; b_++) wq[b_] = g_Wwq[((warp * 4 + b_) * 4 + q) * 32 + lane];
#pragma unroll
        for (int hf = 0; hf < 2; hf++) {
            int ks = q * 2 + hf;
            uint32_t ya[4][4];
            int rr = lane & 15, hk = lane >> 4;
#pragma unroll
            for (int mt = 0; mt < 4; mt++) {
                int r = mt * 16 + rr, ch = ks * 2 + hk;
                ldm4(ya[mt], sbase + OFF_YB + r * 256 + ((ch ^ (r & 7)) << 4));
            }
#pragma unroll
            for (int b_ = 0; b_ < 4; b_++) {
                uint32_t b0 = hf ? wq[b_].z : wq[b_].x;
                uint32_t b1 = hf ? wq[b_].w : wq[b_].y;
#pragma unroll
                for (int mt = 0; mt < 4; mt++) mma16816h(accW[mt][b_], ya[mt], b0, b1);
            }
        }
    }

    // ---- phase 4b: stage wy pairs in smem (bank-conflict-free), then coalesced epilogue ----
    __syncthreads();   // all YB reads complete; TH/YB reusable as WY
    {
        uint32_t* WY = (uint32_t*)(smem + OFF_TH);   // [64 rows][132 words], pairs of cols
#pragma unroll
        for (int b_ = 0; b_ < 4; b_++) {
            int p = warp * 16 + b_ * 4 + t;          // column-pair index 0..127
#pragma unroll
            for (int mt = 0; mt < 4; mt++) {
#pragma unroll
                for (int h_ = 0; h_ < 2; h_++) {
                    int r = mt * 16 + g + h_ * 8;
                    WY[r * 132 + p] = accW[mt][b_][h_];
                }
            }
        }
    }
    __syncthreads();
    {
        const uint32_t* WY = (const uint32_t*)(smem + OFF_TH);
        float4* out4 = (float4*)out;
#pragma unroll
        for (int it = 0; it < 16; it++) {
            int id = tid + it * 256;                 // 0..4095 = 64 rows x 64 float4-cols
            int row = id >> 6, c4 = id & 63;
            uint32_t chn = (uint32_t)((c4 >> 1) ^ (row & 7));
            const char* xb = smem + OFF_XH + row * 512 + chn * 16 + (c4 & 1) * 8;
            uint2 xh2 = *(const uint2*)xb;
            uint2 xl2 = *(const uint2*)(xb + 32768);
            uint2 wy2 = *(const uint2*)(WY + row * 132 + c4 * 2);
            float4 bb = *(const float4*)(b2s + c4 * 4);
            __half2 H0 = *reinterpret_cast<__half2*>(&xh2.x);
            __half2 H1 = *reinterpret_cast<__half2*>(&xh2.y);
            __half2 L0 = *reinterpret_cast<__half2*>(&xl2.x);
            __half2 L1 = *reinterpret_cast<__half2*>(&xl2.y);
            __half2 W0 = *reinterpret_cast<__half2*>(&wy2.x);
            __half2 W1 = *reinterpret_cast<__half2*>(&wy2.y);
            __half2 WL0 = __hadd2(W0, L0);
            __half2 WL1 = __hadd2(W1, L1);
            float4 o;
            o.x = __low2float(WL0)  + bb.x + __low2float(H0);
            o.y = __high2float(WL0) + bb.y + __high2float(H0);
            o.z = __low2float(WL1)  + bb.z + __low2float(H1);
            o.w = __high2float(WL1) + bb.w + __high2float(H1);
            out4[((size_t)blk * 64 + gos[row]) * 64 + c4] = o;
        }
    }
}

extern "C" void kernel_launch(void* const* d_in, const int* in_sizes, int n_in,
                              void* d_out, int out_size) {
    const float* x       = (const float*)d_in[0];
    const int*   grouped = (const int*)d_in[1];
    const float* tw  = (const float*)d_in[3];
    const float* tb  = (const float*)d_in[4];
    const float* pw  = (const float*)d_in[5];
    const float* pb  = (const float*)d_in[6];
    const float* gw  = (const float*)d_in[7];
    const float* gb  = (const float*)d_in[8];
    const float* ww  = (const float*)d_in[9];
    const float* wb  = (const float*)d_in[10];
    const float* gam = (const float*)d_in[11];
    const float* bet = (const float*)d_in[12];
    float* out = (float*)d_out;

    prep_kernel<<<48, 256>>>(tw, tb, pw, pb, gw, gb, ww, wb, gam, bet);
    cudaFuncSetAttribute(nl_kernel, cudaFuncAttributeMaxDynamicSharedMemorySize, SMEM_BYTES);
    nl_kernel<<<4096, 256, SMEM_BYTES>>>(x, grouped, out);
}

// round 15
// speedup vs baseline: 1.4784x; 1.0309x over previous
#include <cuda_runtime.h>
#include <cuda_fp16.h>
#include <cstdint>

#define DI __device__ __forceinline__

// ---------------- persistent prepped weights (mma B-fragment order, 2 ks per uint4) ----------------
__device__ uint4 g_W1q[48 * 8 * 32];
__device__ uint4 g_Wwq[32 * 4 * 32];
__device__ float g_b1[384];
__device__ float g_b2[256];

DI uint32_t packh2(float a, float b) {
    __half2 h = __halves2half2(__float2half_rn(a), __float2half_rn(b));
    return *reinterpret_cast<uint32_t*>(&h);
}

__global__ void prep_kernel(const float* __restrict__ tw, const float* __restrict__ tb,
                            const float* __restrict__ pw, const float* __restrict__ pb,
                            const float* __restrict__ gw, const float* __restrict__ gb,
                            const float* __restrict__ ww, const float* __restrict__ wb,
                            const float* __restrict__ gamma, const float* __restrict__ beta) {
    int idx = blockIdx.x * blockDim.x + threadIdx.x;
    const float inv = rsqrtf(1.0f + 1e-5f);
    if (idx < 48 * 8 * 32) {
        int lane = idx & 31, q = (idx >> 5) & 7, jt = idx >> 8;
        int j = jt * 8 + (lane >> 2);
        int ka = (2 * q) * 16 + (lane & 3) * 2;
        int kb = ka + 16;
        auto W = [&](int jj, int c) -> float {
            return (jj < 128) ? tw[jj * 256 + c]
                 : (jj < 256) ? pw[(jj - 128) * 256 + c]
                              : gw[(jj - 256) * 256 + c];
        };
        uint4 v;
        v.x = packh2(W(j, ka),     W(j, ka + 1));
        v.y = packh2(W(j, ka + 8), W(j, ka + 9));
        v.z = packh2(W(j, kb),     W(j, kb + 1));
        v.w = packh2(W(j, kb + 8), W(j, kb + 9));
        g_W1q[idx] = v;
    }
    if (idx < 32 * 4 * 32) {
        int lane = idx & 31, q = (idx >> 5) & 3, jt = idx >> 7;
        int c = jt * 8 + (lane >> 2);
        int ka = (2 * q) * 16 + (lane & 3) * 2;
        int kb = ka + 16;
        float s = gamma[c] * inv;
        uint4 v;
        v.x = packh2(ww[c * 128 + ka] * s,     ww[c * 128 + ka + 1] * s);
        v.y = packh2(ww[c * 128 + ka + 8] * s, ww[c * 128 + ka + 9] * s);
        v.z = packh2(ww[c * 128 + kb] * s,     ww[c * 128 + kb + 1] * s);
        v.w = packh2(ww[c * 128 + kb + 8] * s, ww[c * 128 + kb + 9] * s);
        g_Wwq[idx] = v;
    }
    if (idx < 384) g_b1[idx] = (idx < 128) ? tb[idx] : ((idx < 256) ? pb[idx - 128] : gb[idx - 256]);
    if (idx < 256) g_b2[idx] = wb[idx] * (gamma[idx] * inv) + beta[idx];
}

// ---------------- helpers ----------------
DI void ldm4(uint32_t* r, uint32_t addr) {
    asm volatile("ldmatrix.sync.aligned.m8n8.x4.shared.b16 {%0,%1,%2,%3}, [%4];\n"
                 : "=r"(r[0]), "=r"(r[1]), "=r"(r[2]), "=r"(r[3]) : "r"(addr));
}
DI void mma16816(float* d, const uint32_t* a, uint32_t b0, uint32_t b1) {
    asm volatile("mma.sync.aligned.m16n8k16.row.col.f32.f16.f16.f32 "
                 "{%0,%1,%2,%3}, {%4,%5,%6,%7}, {%8,%9}, {%0,%1,%2,%3};\n"
                 : "+f"(d[0]), "+f"(d[1]), "+f"(d[2]), "+f"(d[3])
                 : "r"(a[0]), "r"(a[1]), "r"(a[2]), "r"(a[3]), "r"(b0), "r"(b1));
}
DI void mma16816h(uint32_t* d, const uint32_t* a, uint32_t b0, uint32_t b1) {
    asm volatile("mma.sync.aligned.m16n8k16.row.col.f16.f16.f16.f16 "
                 "{%0,%1}, {%2,%3,%4,%5}, {%6,%7}, {%0,%1};\n"
                 : "+r"(d[0]), "+r"(d[1])
                 : "r"(a[0]), "r"(a[1]), "r"(a[2]), "r"(a[3]), "r"(b0), "r"(b1));
}
DI float hmax4(float a, float b, float c, float d) { return fmaxf(fmaxf(a, b), fmaxf(c, d)); }
DI float pool4(float v) {
    v = fmaxf(v, __shfl_xor_sync(0xffffffffu, v, 4));
    v = fmaxf(v, __shfl_xor_sync(0xffffffffu, v, 8));
    return v;
}
DI uint32_t pool4h(uint32_t v) {
    __half2 a = *reinterpret_cast<__half2*>(&v);
    uint32_t u = __shfl_xor_sync(0xffffffffu, v, 4);
    a = __hmax2(a, *reinterpret_cast<__half2*>(&u));
    uint32_t w = *reinterpret_cast<uint32_t*>(&a);
    u = __shfl_xor_sync(0xffffffffu, w, 8);
    a = __hmax2(a, *reinterpret_cast<__half2*>(&u));
    return *reinterpret_cast<uint32_t*>(&a);
}

// ---------------- smem layout (bytes) ----------------
constexpr int OFF_XH = 0;        // half [64][256] swizzled (GEMM1 A, residual hi)  32768 B
constexpr int OFF_TH = 32768;    // half [64][128] swizzled (theta); WY overlay     16384 B
constexpr int OFF_YB = 49152;    // half [64][128] swizzled (y); WY overlay         16384 B
constexpr int OFF_PH = 65536;    // half [16][136] phi pooled (WY clips 1KB; dead)   4352 B
constexpr int OFF_GX = 69888;    // half [128][16] gx pooled (i-major)               4096 B
constexpr int OFF_B1 = 73984;    // float[384]
constexpr int OFF_B2 = 75520;    // float[256]
constexpr int OFF_GO = 76544;    // int[64]
constexpr int SMEM_BYTES = 76800;
// WY: uint32[64][132] at OFF_TH (33792 B, spans TH+YB+1KB of PH; all dead in phase-4 tail)

__global__ void __launch_bounds__(256, 2)
nl_kernel(const float* __restrict__ x, const int* __restrict__ grouped,
          float* __restrict__ out) {
    extern __shared__ char smem[];
    const uint32_t sbase = (uint32_t)__cvta_generic_to_shared(smem);
    float* b1s = (float*)(smem + OFF_B1);
    float* b2s = (float*)(smem + OFF_B2);
    int*   gos = (int*)(smem + OFF_GO);

    const int tid = threadIdx.x, warp = tid >> 5, lane = tid & 31;
    const int g = lane >> 2, t = lane & 3;
    const int blk = blockIdx.x;

    // ---- phase 0: tables ----
    if (tid < 64) gos[tid] = grouped[tid];
    b2s[tid] = g_b2[tid];
    b1s[tid] = g_b1[tid];
    if (tid < 128) b1s[256 + tid] = g_b1[256 + tid];
    __syncthreads();

    // ---- phase 1: gather rows by grouped order; fp16 swizzled copy ----
    {
        const float4* x4 = (const float4*)x;
        uint4* XH4 = (uint4*)(smem + OFF_XH);
#pragma unroll
        for (int it = 0; it < 8; it++) {
            int ci = tid + it * 256;            // 0..2047 : 64 rows x 32 chunks of 8 floats
            int r = ci >> 5, ch = ci & 31;
            size_t rb = ((size_t)blk * 64 + gos[r]) * 64;
            float4 va = x4[rb + ch * 2];
            float4 vb = x4[rb + ch * 2 + 1];
            uint4 w;
            w.x = packh2(va.x, va.y); w.y = packh2(va.z, va.w);
            w.z = packh2(vb.x, vb.y); w.w = packh2(vb.z, vb.w);
            XH4[r * 32 + (ch ^ (r & 7))] = w;
        }
    }
    __syncthreads();

    // ---- phase 2: GEMM1  Out1[64][384] = Xg @ W1^T, single pass ----
    const int colA = warp * 32;
    const int colG = 256 + warp * 16;
    {
        float    accA[4][4][4];
        uint32_t accG[4][2][2];
#pragma unroll
        for (int a_ = 0; a_ < 4; a_++)
#pragma unroll
            for (int b_ = 0; b_ < 4; b_++) {
#pragma unroll
                for (int c_ = 0; c_ < 4; c_++) accA[a_][b_][c_] = 0.f;
                if (b_ < 2) { accG[a_][b_][0] = 0u; accG[a_][b_][1] = 0u; }
            }

        for (int q = 0; q < 8; q++) {
            uint4 wq[4], wg[2];
#pragma unroll
            for (int b_ = 0; b_ < 4; b_++) wq[b_] = g_W1q[((warp * 4 + b_) * 8 + q) * 32 + lane];
#pragma unroll
            for (int b_ = 0; b_ < 2; b_++) wg[b_] = g_W1q[((32 + warp * 2 + b_) * 8 + q) * 32 + lane];
#pragma unroll
            for (int hf = 0; hf < 2; hf++) {
                int ks = q * 2 + hf;
                uint32_t ah[4][4];
                int rr = lane & 15, hk = lane >> 4;
#pragma unroll
                for (int mt = 0; mt < 4; mt++) {
                    int r = mt * 16 + rr, ch = ks * 2 + hk;
                    ldm4(ah[mt], sbase + OFF_XH + r * 512 + ((ch ^ (r & 7)) << 4));
                }
#pragma unroll
                for (int b_ = 0; b_ < 4; b_++) {
                    uint32_t b0 = hf ? wq[b_].z : wq[b_].x;
                    uint32_t b1 = hf ? wq[b_].w : wq[b_].y;
#pragma unroll
                    for (int mt = 0; mt < 4; mt++) mma16816(accA[mt][b_], ah[mt], b0, b1);
                }
#pragma unroll
                for (int b_ = 0; b_ < 2; b_++) {
                    uint32_t b0 = hf ? wg[b_].z : wg[b_].x;
                    uint32_t b1 = hf ? wg[b_].w : wg[b_].y;
#pragma unroll
                    for (int mt = 0; mt < 4; mt++) mma16816h(accG[mt][b_], ah[mt], b0, b1);
                }
            }
        }

        // ---- epilogue: theta store (warps 0-3), phi pool+store (warps 4-7), g pool (all) ----
        uint32_t* TH = (uint32_t*)(smem + OFF_TH);
        uint32_t* PH = (uint32_t*)(smem + OFF_PH);
        __half*   GX = (__half*)(smem + OFF_GX);
#pragma unroll
        for (int b_ = 0; b_ < 4; b_++) {
            int c = colA + b_ * 8 + t * 2;
            float bi0 = b1s[c], bi1 = b1s[c + 1];
#pragma unroll
            for (int mt = 0; mt < 4; mt++) {
                float v00 = accA[mt][b_][0] + bi0, v01 = accA[mt][b_][1] + bi1;
                float v10 = accA[mt][b_][2] + bi0, v11 = accA[mt][b_][3] + bi1;
                if (warp < 4) {
                    int r0 = mt * 16 + g, r1 = r0 + 8;
                    int wd = c >> 1, chn = c >> 3;
                    TH[r0 * 64 + (((chn ^ (r0 & 7)) << 2) | (wd & 3))] = packh2(v00, v01);
                    TH[r1 * 64 + (((chn ^ (r1 & 7)) << 2) | (wd & 3))] = packh2(v10, v11);
                } else {
                    v00 = pool4(v00); v01 = pool4(v01);
                    v10 = pool4(v10); v11 = pool4(v11);
                    if ((g & 3) == 0) {
                        int i = c - 128;
                        int p01 = mt * 4 + (g >> 2), p23 = p01 + 2;
                        PH[p01 * 68 + (i >> 1)] = packh2(v00, v01);
                        PH[p23 * 68 + (i >> 1)] = packh2(v10, v11);
                    }
                }
            }
        }
        // g pooled (f16 accums) -> GX[i][p]
#pragma unroll
        for (int b_ = 0; b_ < 2; b_++) {
            int c = colG + b_ * 8 + t * 2;
            int i = c - 256;
            float bi0 = b1s[c], bi1 = b1s[c + 1];
#pragma unroll
            for (int mt = 0; mt < 4; mt++) {
                uint32_t u0 = pool4h(accG[mt][b_][0]);
                uint32_t u1 = pool4h(accG[mt][b_][1]);
                if ((g & 3) == 0) {
                    __half2 h0 = *reinterpret_cast<__half2*>(&u0);
                    __half2 h1 = *reinterpret_cast<__half2*>(&u1);
                    float v00 = __low2float(h0) + bi0, v01 = __high2float(h0) + bi1;
                    float v10 = __low2float(h1) + bi0, v11 = __high2float(h1) + bi1;
                    int p01 = mt * 4 + (g >> 2), p23 = p01 + 2;
                    GX[i * 16 + p01]       = __float2half_rn(v00);
                    GX[(i + 1) * 16 + p01] = __float2half_rn(v01);
                    GX[i * 16 + p23]       = __float2half_rn(v10);
                    GX[(i + 1) * 16 + p23] = __float2half_rn(v11);
                }
            }
        }
    }
    __syncthreads();

    // ---- phase 3 (warps 0-3): f = theta @ phiP^T, softmax, y = a @ gx ----
    if (warp < 4) {
        float accF[2][4];
#pragma unroll
        for (int n_ = 0; n_ < 2; n_++)
#pragma unroll
            for (int c_ = 0; c_ < 4; c_++) accF[n_][c_] = 0.f;

        const __half* PHh = (const __half*)(smem + OFF_PH);
        for (int ks = 0; ks < 8; ks++) {
            uint32_t th[4];
            int r = warp * 16 + (lane & 15), ch = ks * 2 + (lane >> 4);
            ldm4(th, sbase + OFF_TH + r * 256 + ((ch ^ (r & 7)) << 4));
#pragma unroll
            for (int n_ = 0; n_ < 2; n_++) {
                int m = n_ * 8 + g;
                const uint32_t* bh = (const uint32_t*)(PHh + m * 136 + ks * 16 + t * 2);
                mma16816(accF[n_], th, bh[0], bh[4]);
            }
        }
        float a0 = accF[0][0], a1 = accF[0][1], a2 = accF[1][0], a3 = accF[1][1];
        float c0 = accF[0][2], c1 = accF[0][3], c2 = accF[1][2], c3 = accF[1][3];
        float mA = hmax4(a0, a1, a2, a3), mB = hmax4(c0, c1, c2, c3);
        mA = fmaxf(mA, __shfl_xor_sync(0xffffffffu, mA, 1));
        mA = fmaxf(mA, __shfl_xor_sync(0xffffffffu, mA, 2));
        mB = fmaxf(mB, __shfl_xor_sync(0xffffffffu, mB, 1));
        mB = fmaxf(mB, __shfl_xor_sync(0xffffffffu, mB, 2));
        a0 = __expf(a0 - mA); a1 = __expf(a1 - mA); a2 = __expf(a2 - mA); a3 = __expf(a3 - mA);
        c0 = __expf(c0 - mB); c1 = __expf(c1 - mB); c2 = __expf(c2 - mB); c3 = __expf(c3 - mB);
        float sA = a0 + a1 + a2 + a3, sB = c0 + c1 + c2 + c3;
        sA += __shfl_xor_sync(0xffffffffu, sA, 1);
        sA += __shfl_xor_sync(0xffffffffu, sA, 2);
        sB += __shfl_xor_sync(0xffffffffu, sB, 1);
        sB += __shfl_xor_sync(0xffffffffu, sB, 2);
        float iA = 1.0f / sA, iB = 1.0f / sB;
        a0 *= iA; a1 *= iA; a2 *= iA; a3 *= iA;
        c0 *= iB; c1 *= iB; c2 *= iB; c3 *= iB;
        uint32_t fa[4];
        fa[0] = packh2(a0, a1); fa[1] = packh2(c0, c1);
        fa[2] = packh2(a2, a3); fa[3] = packh2(c2, c3);

        float accY[16][4];
#pragma unroll
        for (int nt = 0; nt < 16; nt++)
#pragma unroll
            for (int c_ = 0; c_ < 4; c_++) accY[nt][c_] = 0.f;
        const __half* GX = (const __half*)(smem + OFF_GX);
#pragma unroll
        for (int nt = 0; nt < 16; nt++) {
            int irow = nt * 8 + g;
            const uint32_t* bp = (const uint32_t*)(GX + irow * 16 + t * 2);
            mma16816(accY[nt], fa, bp[0], bp[4]);
        }
        uint32_t* YB = (uint32_t*)(smem + OFF_YB);
        int r0 = warp * 16 + g, r1 = r0 + 8;
#pragma unroll
        for (int nt = 0; nt < 16; nt++) {
            YB[r0 * 64 + (((nt ^ (r0 & 7)) << 2) | t)] = packh2(accY[nt][0], accY[nt][1]);
            YB[r1 * 64 + (((nt ^ (r1 & 7)) << 2) | t)] = packh2(accY[nt][2], accY[nt][3]);
        }
    }
    __syncthreads();

    // ---- phase 4: wy[64][256] = y @ Ww^T (f16 acc) ----
    uint32_t accW[4][4][2];
#pragma unroll
    for (int a_ = 0; a_ < 4; a_++)
#pragma unroll
        for (int b_ = 0; b_ < 4; b_++) { accW[a_][b_][0] = 0u; accW[a_][b_][1] = 0u; }

    for (int q = 0; q < 4; q++) {
        uint4 wq[4];
#pragma unroll
        for (int b_ = 0; b_ < 4; b_++) wq[b_] = g_Wwq[((warp * 4 + b_) * 4 + q) * 32 + lane];
#pragma unroll
        for (int hf = 0; hf < 2; hf++) {
            int ks = q * 2 + hf;
            uint32_t ya[4][4];
            int rr = lane & 15, hk = lane >> 4;
#pragma unroll
            for (int mt = 0; mt < 4; mt++) {
                int r = mt * 16 + rr, ch = ks * 2 + hk;
                ldm4(ya[mt], sbase + OFF_YB + r * 256 + ((ch ^ (r & 7)) << 4));
            }
#pragma unroll
            for (int b_ = 0; b_ < 4; b_++) {
                uint32_t b0 = hf ? wq[b_].z : wq[b_].x;
                uint32_t b1 = hf ? wq[b_].w : wq[b_].y;
#pragma unroll
                for (int mt = 0; mt < 4; mt++) mma16816h(accW[mt][b_], ya[mt], b0, b1);
            }
        }
    }

    // ---- phase 4b: stage wy pairs in smem (bank-conflict-free), then coalesced epilogue ----
    __syncthreads();   // all YB reads complete; TH/YB (+1KB of PH) reusable as WY
    {
        uint32_t* WY = (uint32_t*)(smem + OFF_TH);   // [64 rows][132 words], pairs of cols
#pragma unroll
        for (int b_ = 0; b_ < 4; b_++) {
            int p = warp * 16 + b_ * 4 + t;          // column-pair index 0..127
#pragma unroll
            for (int mt = 0; mt < 4; mt++) {
#pragma unroll
                for (int h_ = 0; h_ < 2; h_++) {
                    int r = mt * 16 + g + h_ * 8;
                    WY[r * 132 + p] = accW[mt][b_][h_];
                }
            }
        }
    }
    __syncthreads();
    {
        const uint32_t* WY = (const uint32_t*)(smem + OFF_TH);
        float4* out4 = (float4*)out;
#pragma unroll
        for (int it = 0; it < 16; it++) {
            int id = tid + it * 256;                 // 0..4095 = 64 rows x 64 float4-cols
            int row = id >> 6, c4 = id & 63;
            uint32_t chn = (uint32_t)((c4 >> 1) ^ (row & 7));
            const char* xb = smem + OFF_XH + row * 512 + chn * 16 + (c4 & 1) * 8;
            uint2 xh2 = *(const uint2*)xb;
            uint2 wy2 = *(const uint2*)(WY + row * 132 + c4 * 2);
            float4 bb = *(const float4*)(b2s + c4 * 4);
            __half2 H0 = *reinterpret_cast<__half2*>(&xh2.x);
            __half2 H1 = *reinterpret_cast<__half2*>(&xh2.y);
            __half2 W0 = *reinterpret_cast<__half2*>(&wy2.x);
            __half2 W1 = *reinterpret_cast<__half2*>(&wy2.y);
            float4 o;
            o.x = __low2float(W0)  + bb.x + __low2float(H0);
            o.y = __high2float(W0) + bb.y + __high2float(H0);
            o.z = __low2float(W1)  + bb.z + __low2float(H1);
            o.w = __high2float(W1) + bb.w + __high2float(H1);
            out4[((size_t)blk * 64 + gos[row]) * 64 + c4] = o;
        }
    }
}

extern "C" void kernel_launch(void* const* d_in, const int* in_sizes, int n_in,
                              void* d_out, int out_size) {
    const float* x       = (const float*)d_in[0];
    const int*   grouped = (const int*)d_in[1];
    const float* tw  = (const float*)d_in[3];
    const float* tb  = (const float*)d_in[4];
    const float* pw  = (const float*)d_in[5];
    const float* pb  = (const float*)d_in[6];
    const float* gw  = (const float*)d_in[7];
    const float* gb  = (const float*)d_in[8];
    const float* ww  = (const float*)d_in[9];
    const float* wb  = (const float*)d_in[10];
    const float* gam = (const float*)d_in[11];
    const float* bet = (const float*)d_in[12];
    float* out = (float*)d_out;

    prep_kernel<<<48, 256>>>(tw, tb, pw, pb, gw, gb, ww, wb, gam, bet);
    cudaFuncSetAttribute(nl_kernel, cudaFuncAttributeMaxDynamicSharedMemorySize, SMEM_BYTES);
    nl_kernel<<<4096, 256, SMEM_BYTES>>>(x, grouped, out);
}

// round 16
// speedup vs baseline: 1.5020x; 1.0160x over previous
#include <cuda_runtime.h>
#include <cuda_fp16.h>
#include <cstdint>

#define DI __device__ __forceinline__

// ---------------- persistent prepped weights (mma B-fragment order, 2 ks per uint4) ----------------
__device__ uint4 g_W1q[48 * 8 * 32];
__device__ uint4 g_Wwq[32 * 4 * 32];
__device__ float g_b1[384];
__device__ float g_b2[256];

DI uint32_t packh2(float a, float b) {
    __half2 h = __halves2half2(__float2half_rn(a), __float2half_rn(b));
    return *reinterpret_cast<uint32_t*>(&h);
}

__global__ void prep_kernel(const float* __restrict__ tw, const float* __restrict__ tb,
                            const float* __restrict__ pw, const float* __restrict__ pb,
                            const float* __restrict__ gw, const float* __restrict__ gb,
                            const float* __restrict__ ww, const float* __restrict__ wb,
                            const float* __restrict__ gamma, const float* __restrict__ beta) {
    int idx = blockIdx.x * blockDim.x + threadIdx.x;
    const float inv = rsqrtf(1.0f + 1e-5f);
    if (idx < 48 * 8 * 32) {
        int lane = idx & 31, q = (idx >> 5) & 7, jt = idx >> 8;
        int j = jt * 8 + (lane >> 2);
        int ka = (2 * q) * 16 + (lane & 3) * 2;
        int kb = ka + 16;
        auto W = [&](int jj, int c) -> float {
            return (jj < 128) ? tw[jj * 256 + c]
                 : (jj < 256) ? pw[(jj - 128) * 256 + c]
                              : gw[(jj - 256) * 256 + c];
        };
        uint4 v;
        v.x = packh2(W(j, ka),     W(j, ka + 1));
        v.y = packh2(W(j, ka + 8), W(j, ka + 9));
        v.z = packh2(W(j, kb),     W(j, kb + 1));
        v.w = packh2(W(j, kb + 8), W(j, kb + 9));
        g_W1q[idx] = v;
    }
    if (idx < 32 * 4 * 32) {
        int lane = idx & 31, q = (idx >> 5) & 3, jt = idx >> 7;
        int c = jt * 8 + (lane >> 2);
        int ka = (2 * q) * 16 + (lane & 3) * 2;
        int kb = ka + 16;
        float s = gamma[c] * inv;
        uint4 v;
        v.x = packh2(ww[c * 128 + ka] * s,     ww[c * 128 + ka + 1] * s);
        v.y = packh2(ww[c * 128 + ka + 8] * s, ww[c * 128 + ka + 9] * s);
        v.z = packh2(ww[c * 128 + kb] * s,     ww[c * 128 + kb + 1] * s);
        v.w = packh2(ww[c * 128 + kb + 8] * s, ww[c * 128 + kb + 9] * s);
        g_Wwq[idx] = v;
    }
    if (idx < 384) g_b1[idx] = (idx < 128) ? tb[idx] : ((idx < 256) ? pb[idx - 128] : gb[idx - 256]);
    if (idx < 256) g_b2[idx] = wb[idx] * (gamma[idx] * inv) + beta[idx];
}

// ---------------- helpers ----------------
DI void ldm4(uint32_t* r, uint32_t addr) {
    asm volatile("ldmatrix.sync.aligned.m8n8.x4.shared.b16 {%0,%1,%2,%3}, [%4];\n"
                 : "=r"(r[0]), "=r"(r[1]), "=r"(r[2]), "=r"(r[3]) : "r"(addr));
}
DI void mma16816(float* d, const uint32_t* a, uint32_t b0, uint32_t b1) {
    asm volatile("mma.sync.aligned.m16n8k16.row.col.f32.f16.f16.f32 "
                 "{%0,%1,%2,%3}, {%4,%5,%6,%7}, {%8,%9}, {%0,%1,%2,%3};\n"
                 : "+f"(d[0]), "+f"(d[1]), "+f"(d[2]), "+f"(d[3])
                 : "r"(a[0]), "r"(a[1]), "r"(a[2]), "r"(a[3]), "r"(b0), "r"(b1));
}
DI void mma16816h(uint32_t* d, const uint32_t* a, uint32_t b0, uint32_t b1) {
    asm volatile("mma.sync.aligned.m16n8k16.row.col.f16.f16.f16.f16 "
                 "{%0,%1}, {%2,%3,%4,%5}, {%6,%7}, {%0,%1};\n"
                 : "+r"(d[0]), "+r"(d[1])
                 : "r"(a[0]), "r"(a[1]), "r"(a[2]), "r"(a[3]), "r"(b0), "r"(b1));
}
DI float hmax4(float a, float b, float c, float d) { return fmaxf(fmaxf(a, b), fmaxf(c, d)); }
DI float pool4(float v) {
    v = fmaxf(v, __shfl_xor_sync(0xffffffffu, v, 4));
    v = fmaxf(v, __shfl_xor_sync(0xffffffffu, v, 8));
    return v;
}
DI uint32_t pool4h(uint32_t v) {
    __half2 a = *reinterpret_cast<__half2*>(&v);
    uint32_t u = __shfl_xor_sync(0xffffffffu, v, 4);
    a = __hmax2(a, *reinterpret_cast<__half2*>(&u));
    uint32_t w = *reinterpret_cast<uint32_t*>(&a);
    u = __shfl_xor_sync(0xffffffffu, w, 8);
    a = __hmax2(a, *reinterpret_cast<__half2*>(&u));
    return *reinterpret_cast<uint32_t*>(&a);
}

// ---------------- smem layout (bytes) ----------------
// Padded strides (no XOR swizzle): XH rows 528 B (264 half), TH/YB rows 272 B (136 half).
// 528 % 128 = 16, 272 % 128 = 16 -> consecutive rows shift 4 banks; any 8-row ldmatrix
// phase hits 8 distinct bank groups -> conflict-free.
constexpr int OFF_XH = 0;        // half [64][264]                                  33792 B
constexpr int OFF_TH = 33792;    // half [64][136] (theta); WY overlay              17408 B
constexpr int OFF_YB = 51200;    // half [64][136] (y); WY overlay                  17408 B
constexpr int OFF_PH = 68608;    // half [16][136] phi pooled                        4352 B
constexpr int OFF_GX = 72960;    // half [128][16] gx pooled (i-major)               4096 B
constexpr int OFF_B1 = 77056;    // float[384]
constexpr int OFF_B2 = 78592;    // float[256]
constexpr int OFF_GO = 79616;    // int[64]
constexpr int SMEM_BYTES = 79872;
// WY: uint32[64][132] at OFF_TH (33792 B, spans TH+YB; both dead in phase-4 tail)

__global__ void __launch_bounds__(256, 2)
nl_kernel(const float* __restrict__ x, const int* __restrict__ grouped,
          float* __restrict__ out) {
    extern __shared__ char smem[];
    const uint32_t sbase = (uint32_t)__cvta_generic_to_shared(smem);
    float* b1s = (float*)(smem + OFF_B1);
    float* b2s = (float*)(smem + OFF_B2);
    int*   gos = (int*)(smem + OFF_GO);

    const int tid = threadIdx.x, warp = tid >> 5, lane = tid & 31;
    const int g = lane >> 2, t = lane & 3;
    const int blk = blockIdx.x;

    // ---- phase 0: tables ----
    if (tid < 64) gos[tid] = grouped[tid];
    b2s[tid] = g_b2[tid];
    b1s[tid] = g_b1[tid];
    if (tid < 128) b1s[256 + tid] = g_b1[256 + tid];
    __syncthreads();

    // ---- phase 1: gather rows by grouped order; fp16 copy, padded stride ----
    {
        const float4* x4 = (const float4*)x;
        uint4* XH4 = (uint4*)(smem + OFF_XH);
#pragma unroll
        for (int it = 0; it < 8; it++) {
            int ci = tid + it * 256;            // 0..2047 : 64 rows x 32 chunks of 8 floats
            int r = ci >> 5, ch = ci & 31;
            size_t rb = ((size_t)blk * 64 + gos[r]) * 64;
            float4 va = x4[rb + ch * 2];
            float4 vb = x4[rb + ch * 2 + 1];
            uint4 w;
            w.x = packh2(va.x, va.y); w.y = packh2(va.z, va.w);
            w.z = packh2(vb.x, vb.y); w.w = packh2(vb.z, vb.w);
            XH4[r * 33 + ch] = w;               // 33 uint4 = 528 B stride
        }
    }
    __syncthreads();

    // ---- phase 2: GEMM1  Out1[64][384] = Xg @ W1^T, single pass ----
    const int colA = warp * 32;
    const int colG = 256 + warp * 16;
    {
        float    accA[4][4][4];
        uint32_t accG[4][2][2];
#pragma unroll
        for (int a_ = 0; a_ < 4; a_++)
#pragma unroll
            for (int b_ = 0; b_ < 4; b_++) {
#pragma unroll
                for (int c_ = 0; c_ < 4; c_++) accA[a_][b_][c_] = 0.f;
                if (b_ < 2) { accG[a_][b_][0] = 0u; accG[a_][b_][1] = 0u; }
            }

        for (int q = 0; q < 8; q++) {
            uint4 wq[4], wg[2];
#pragma unroll
            for (int b_ = 0; b_ < 4; b_++) wq[b_] = g_W1q[((warp * 4 + b_) * 8 + q) * 32 + lane];
#pragma unroll
            for (int b_ = 0; b_ < 2; b_++) wg[b_] = g_W1q[((32 + warp * 2 + b_) * 8 + q) * 32 + lane];
#pragma unroll
            for (int hf = 0; hf < 2; hf++) {
                int ks = q * 2 + hf;
                uint32_t ah[4][4];
                int rr = lane & 15, hk = lane >> 4;
#pragma unroll
                for (int mt = 0; mt < 4; mt++) {
                    int r = mt * 16 + rr, ch = ks * 2 + hk;
                    ldm4(ah[mt], sbase + OFF_XH + r * 528 + ch * 16);
                }
#pragma unroll
                for (int b_ = 0; b_ < 4; b_++) {
                    uint32_t b0 = hf ? wq[b_].z : wq[b_].x;
                    uint32_t b1 = hf ? wq[b_].w : wq[b_].y;
#pragma unroll
                    for (int mt = 0; mt < 4; mt++) mma16816(accA[mt][b_], ah[mt], b0, b1);
                }
#pragma unroll
                for (int b_ = 0; b_ < 2; b_++) {
                    uint32_t b0 = hf ? wg[b_].z : wg[b_].x;
                    uint32_t b1 = hf ? wg[b_].w : wg[b_].y;
#pragma unroll
                    for (int mt = 0; mt < 4; mt++) mma16816h(accG[mt][b_], ah[mt], b0, b1);
                }
            }
        }

        // ---- epilogue: theta store (warps 0-3), phi pool+store (warps 4-7), g pool (all) ----
        uint32_t* TH = (uint32_t*)(smem + OFF_TH);
        uint32_t* PH = (uint32_t*)(smem + OFF_PH);
        __half*   GX = (__half*)(smem + OFF_GX);
#pragma unroll
        for (int b_ = 0; b_ < 4; b_++) {
            int c = colA + b_ * 8 + t * 2;
            float bi0 = b1s[c], bi1 = b1s[c + 1];
#pragma unroll
            for (int mt = 0; mt < 4; mt++) {
                float v00 = accA[mt][b_][0] + bi0, v01 = accA[mt][b_][1] + bi1;
                float v10 = accA[mt][b_][2] + bi0, v11 = accA[mt][b_][3] + bi1;
                if (warp < 4) {
                    int r0 = mt * 16 + g, r1 = r0 + 8;
                    int wd = c >> 1;                 // word index 0..63
                    TH[r0 * 68 + wd] = packh2(v00, v01);
                    TH[r1 * 68 + wd] = packh2(v10, v11);
                } else {
                    v00 = pool4(v00); v01 = pool4(v01);
                    v10 = pool4(v10); v11 = pool4(v11);
                    if ((g & 3) == 0) {
                        int i = c - 128;
                        int p01 = mt * 4 + (g >> 2), p23 = p01 + 2;
                        PH[p01 * 68 + (i >> 1)] = packh2(v00, v01);
                        PH[p23 * 68 + (i >> 1)] = packh2(v10, v11);
                    }
                }
            }
        }
        // g pooled (f16 accums) -> GX[i][p]
#pragma unroll
        for (int b_ = 0; b_ < 2; b_++) {
            int c = colG + b_ * 8 + t * 2;
            int i = c - 256;
            float bi0 = b1s[c], bi1 = b1s[c + 1];
#pragma unroll
            for (int mt = 0; mt < 4; mt++) {
                uint32_t u0 = pool4h(accG[mt][b_][0]);
                uint32_t u1 = pool4h(accG[mt][b_][1]);
                if ((g & 3) == 0) {
                    __half2 h0 = *reinterpret_cast<__half2*>(&u0);
                    __half2 h1 = *reinterpret_cast<__half2*>(&u1);
                    float v00 = __low2float(h0) + bi0, v01 = __high2float(h0) + bi1;
                    float v10 = __low2float(h1) + bi0, v11 = __high2float(h1) + bi1;
                    int p01 = mt * 4 + (g >> 2), p23 = p01 + 2;
                    GX[i * 16 + p01]       = __float2half_rn(v00);
                    GX[(i + 1) * 16 + p01] = __float2half_rn(v01);
                    GX[i * 16 + p23]       = __float2half_rn(v10);
                    GX[(i + 1) * 16 + p23] = __float2half_rn(v11);
                }
            }
        }
    }
    __syncthreads();

    // ---- phase 3 (warps 0-3): f = theta @ phiP^T, softmax, y = a @ gx ----
    if (warp < 4) {
        float accF[2][4];
#pragma unroll
        for (int n_ = 0; n_ < 2; n_++)
#pragma unroll
            for (int c_ = 0; c_ < 4; c_++) accF[n_][c_] = 0.f;

        const __half* PHh = (const __half*)(smem + OFF_PH);
        for (int ks = 0; ks < 8; ks++) {
            uint32_t th[4];
            int r = warp * 16 + (lane & 15), ch = ks * 2 + (lane >> 4);
            ldm4(th, sbase + OFF_TH + r * 272 + ch * 16);
#pragma unroll
            for (int n_ = 0; n_ < 2; n_++) {
                int m = n_ * 8 + g;
                const uint32_t* bh = (const uint32_t*)(PHh + m * 136 + ks * 16 + t * 2);
                mma16816(accF[n_], th, bh[0], bh[4]);
            }
        }
        float a0 = accF[0][0], a1 = accF[0][1], a2 = accF[1][0], a3 = accF[1][1];
        float c0 = accF[0][2], c1 = accF[0][3], c2 = accF[1][2], c3 = accF[1][3];
        float mA = hmax4(a0, a1, a2, a3), mB = hmax4(c0, c1, c2, c3);
        mA = fmaxf(mA, __shfl_xor_sync(0xffffffffu, mA, 1));
        mA = fmaxf(mA, __shfl_xor_sync(0xffffffffu, mA, 2));
        mB = fmaxf(mB, __shfl_xor_sync(0xffffffffu, mB, 1));
        mB = fmaxf(mB, __shfl_xor_sync(0xffffffffu, mB, 2));
        a0 = __expf(a0 - mA); a1 = __expf(a1 - mA); a2 = __expf(a2 - mA); a3 = __expf(a3 - mA);
        c0 = __expf(c0 - mB); c1 = __expf(c1 - mB); c2 = __expf(c2 - mB); c3 = __expf(c3 - mB);
        float sA = a0 + a1 + a2 + a3, sB = c0 + c1 + c2 + c3;
        sA += __shfl_xor_sync(0xffffffffu, sA, 1);
        sA += __shfl_xor_sync(0xffffffffu, sA, 2);
        sB += __shfl_xor_sync(0xffffffffu, sB, 1);
        sB += __shfl_xor_sync(0xffffffffu, sB, 2);
        float iA = 1.0f / sA, iB = 1.0f / sB;
        a0 *= iA; a1 *= iA; a2 *= iA; a3 *= iA;
        c0 *= iB; c1 *= iB; c2 *= iB; c3 *= iB;
        uint32_t fa[4];
        fa[0] = packh2(a0, a1); fa[1] = packh2(c0, c1);
        fa[2] = packh2(a2, a3); fa[3] = packh2(c2, c3);

        float accY[16][4];
#pragma unroll
        for (int nt = 0; nt < 16; nt++)
#pragma unroll
            for (int c_ = 0; c_ < 4; c_++) accY[nt][c_] = 0.f;
        const __half* GX = (const __half*)(smem + OFF_GX);
#pragma unroll
        for (int nt = 0; nt < 16; nt++) {
            int irow = nt * 8 + g;
            const uint32_t* bp = (const uint32_t*)(GX + irow * 16 + t * 2);
            mma16816(accY[nt], fa, bp[0], bp[4]);
        }
        uint32_t* YB = (uint32_t*)(smem + OFF_YB);
        int r0 = warp * 16 + g, r1 = r0 + 8;
#pragma unroll
        for (int nt = 0; nt < 16; nt++) {
            YB[r0 * 68 + nt * 4 + t] = packh2(accY[nt][0], accY[nt][1]);
            YB[r1 * 68 + nt * 4 + t] = packh2(accY[nt][2], accY[nt][3]);
        }
    }
    __syncthreads();

    // ---- phase 4: wy[64][256] = y @ Ww^T (f16 acc) ----
    uint32_t accW[4][4][2];
#pragma unroll
    for (int a_ = 0; a_ < 4; a_++)
#pragma unroll
        for (int b_ = 0; b_ < 4; b_++) { accW[a_][b_][0] = 0u; accW[a_][b_][1] = 0u; }

    for (int q = 0; q < 4; q++) {
        uint4 wq[4];
#pragma unroll
        for (int b_ = 0; b_ < 4; b_++) wq[b_] = g_Wwq[((warp * 4 + b_) * 4 + q) * 32 + lane];
#pragma unroll
        for (int hf = 0; hf < 2; hf++) {
            int ks = q * 2 + hf;
            uint32_t ya[4][4];
            int rr = lane & 15, hk = lane >> 4;
#pragma unroll
            for (int mt = 0; mt < 4; mt++) {
                int r = mt * 16 + rr, ch = ks * 2 + hk;
                ldm4(ya[mt], sbase + OFF_YB + r * 272 + ch * 16);
            }
#pragma unroll
            for (int b_ = 0; b_ < 4; b_++) {
                uint32_t b0 = hf ? wq[b_].z : wq[b_].x;
                uint32_t b1 = hf ? wq[b_].w : wq[b_].y;
#pragma unroll
                for (int mt = 0; mt < 4; mt++) mma16816h(accW[mt][b_], ya[mt], b0, b1);
            }
        }
    }

    // ---- phase 4b: stage wy pairs in smem (bank-conflict-free), then coalesced epilogue ----
    __syncthreads();   // all YB reads complete; TH/YB reusable as WY
    {
        uint32_t* WY = (uint32_t*)(smem + OFF_TH);   // [64 rows][132 words], pairs of cols
#pragma unroll
        for (int b_ = 0; b_ < 4; b_++) {
            int p = warp * 16 + b_ * 4 + t;          // column-pair index 0..127
#pragma unroll
            for (int mt = 0; mt < 4; mt++) {
#pragma unroll
                for (int h_ = 0; h_ < 2; h_++) {
                    int r = mt * 16 + g + h_ * 8;
                    WY[r * 132 + p] = accW[mt][b_][h_];
                }
            }
        }
    }
    __syncthreads();
    {
        const uint32_t* WY = (const uint32_t*)(smem + OFF_TH);
        float4* out4 = (float4*)out;
#pragma unroll
        for (int it = 0; it < 16; it++) {
            int id = tid + it * 256;                 // 0..4095 = 64 rows x 64 float4-cols
            int row = id >> 6, c4 = id & 63;
            const char* xb = smem + OFF_XH + row * 528 + c4 * 8;
            uint2 xh2 = *(const uint2*)xb;
            uint2 wy2 = *(const uint2*)(WY + row * 132 + c4 * 2);
            float4 bb = *(const float4*)(b2s + c4 * 4);
            __half2 H0 = *reinterpret_cast<__half2*>(&xh2.x);
            __half2 H1 = *reinterpret_cast<__half2*>(&xh2.y);
            __half2 W0 = *reinterpret_cast<__half2*>(&wy2.x);
            __half2 W1 = *reinterpret_cast<__half2*>(&wy2.y);
            float4 o;
            o.x = __low2float(W0)  + bb.x + __low2float(H0);
            o.y = __high2float(W0) + bb.y + __high2float(H0);
            o.z = __low2float(W1)  + bb.z + __low2float(H1);
            o.w = __high2float(W1) + bb.w + __high2float(H1);
            out4[((size_t)blk * 64 + gos[row]) * 64 + c4] = o;
        }
    }
}

extern "C" void kernel_launch(void* const* d_in, const int* in_sizes, int n_in,
                              void* d_out, int out_size) {
    const float* x       = (const float*)d_in[0];
    const int*   grouped = (const int*)d_in[1];
    const float* tw  = (const float*)d_in[3];
    const float* tb  = (const float*)d_in[4];
    const float* pw  = (const float*)d_in[5];
    const float* pb  = (const float*)d_in[6];
    const float* gw  = (const float*)d_in[7];
    const float* gb  = (const float*)d_in[8];
    const float* ww  = (const float*)d_in[9];
    const float* wb  = (const float*)d_in[10];
    const float* gam = (const float*)d_in[11];
    const float* bet = (const float*)d_in[12];
    float* out = (float*)d_out;

    prep_kernel<<<48, 256>>>(tw, tb, pw, pb, gw, gb, ww, wb, gam, bet);
    cudaFuncSetAttribute(nl_kernel, cudaFuncAttributeMaxDynamicSharedMemorySize, SMEM_BYTES);
    nl_kernel<<<4096, 256, SMEM_BYTES>>>(x, grouped, out);
}